// round 12
// baseline (speedup 1.0000x reference)
#include <cuda_runtime.h>
#include <cuda_bf16.h>
#include <cstdint>

#define BB 32
#define TT 48
#define LL 400
#define VV 32000
#define EXT_V 32050
#define NBLK 148

typedef unsigned long long u64;

// ---------------- persistent device state ----------------
__device__ float g_Wcat0[1024 * 768];   // [Wih0 | Whh0]
__device__ float g_Wcat1[1024 * 512];   // [Wih1 | Whh1]
__device__ float g_bsum0[1024];
__device__ float g_bsum1[1024];
__device__ float g_h0T[2][8192];        // [parity][j*32+b]
__device__ float g_h1T[2][8192];
__device__ float g_c0[8192];            // [j*32+b], in-place
__device__ float g_c1[8192];
__device__ float g_pout[8192];          // dec_out / prev_out, [b*256+e]
__device__ float g_gate[BB];
__device__ float g_sum[BB];
__device__ unsigned g_cnt;              // arrival counter (reset each replay in kInit)
__device__ float g_scr[BB * VV];        // exp(logits), [b][v]
__device__ float g_add[BB * EXT_V];     // copy-scatter buffer

__device__ __forceinline__ float sigf(float x) { return 1.0f / (1.0f + __expf(-x)); }

__device__ __forceinline__ u64 ffma2(u64 a, u64 b, u64 c) {
    u64 r;
    asm("fma.rn.f32x2 %0, %1, %2, %3;" : "=l"(r) : "l"(a), "l"(b), "l"(c));
    return r;
}
__device__ __forceinline__ float sum2(u64 v) {
    float a, b;
    asm("mov.b64 {%0, %1}, %2;" : "=f"(a), "=f"(b) : "l"(v));
    return a + b;
}

// ---------------- prep: concat weights, sum biases ----------------
__global__ void __launch_bounds__(256) kPrep(
        const float* __restrict__ Wih0, const float* __restrict__ Whh0,
        const float* __restrict__ bih0, const float* __restrict__ bhh0,
        const float* __restrict__ Wih1, const float* __restrict__ Whh1,
        const float* __restrict__ bih1, const float* __restrict__ bhh1) {
    int i = blockIdx.x * 256 + threadIdx.x;
    if (i < 1024 * 768) {
        int r = i / 768, k = i - r * 768;
        g_Wcat0[i] = (k < 512) ? Wih0[r * 512 + k] : Whh0[r * 256 + (k - 512)];
        return;
    }
    int j = i - 1024 * 768;
    if (j < 1024 * 512) {
        int r = j / 512, k = j - r * 512;
        g_Wcat1[j] = (k < 256) ? Wih1[r * 256 + k] : Whh1[r * 256 + (k - 256)];
        return;
    }
    int m = j - 1024 * 512;
    if (m < 1024) g_bsum0[m] = bih0[m] + bhh0[m];
    else if (m < 2048) g_bsum1[m - 1024] = bih1[m - 1024] + bhh1[m - 1024];
}

// ---------------- init state (every replay) ----------------
__global__ void __launch_bounds__(256) kInit(
        const float* __restrict__ h0, const float* __restrict__ c0,
        const float* __restrict__ pout) {
    int i = blockIdx.x * 256 + threadIdx.x;   // i = b*256 + j
    if (i == 0) g_cnt = 0u;
    if (i >= 8192) return;
    int b = i >> 8, j = i & 255;
    g_h0T[0][j * 32 + b] = h0[i];
    g_h1T[0][j * 32 + b] = h0[8192 + i];
    g_c0[j * 32 + b] = c0[i];
    g_c1[j * 32 + b] = c0[8192 + i];
    g_pout[i] = pout[i];
}

// ---------------- LSTM gates + activations (layer 0 or 1) ----------------
// grid 128, block 256. Block owns units j0=blk*2, j0+1. warp w: u=w&1 (unit),
// q=w>>1 (K-quarter); warp computes all 4 gate rows of its unit over its
// K-quarter (4 FMA per x-LDS). Activations fused in tail.
template<int LAYER>
__global__ void __launch_bounds__(256) kGates(
        const float* __restrict__ emb, const int* __restrict__ abstract,
        const int* __restrict__ extend_art, int t) {
    constexpr int K = (LAYER == 0) ? 768 : 512;
    constexpr int KQ = K / 4;
    extern __shared__ float xs[];                 // [K][33]
    __shared__ float part[4][2][4][32];           // [gate][unit][quarter][batch]
    __shared__ int toks[32];
    const int tid = threadIdx.x;
    const int p = t & 1;

    if (LAYER == 0) {
        // zero copy-scatter targets for this step (positions are static per batch)
        int gid = blockIdx.x * 256 + tid;
        if (gid < BB * LL) {
            int b = gid / LL, l = gid - b * LL;
            g_add[b * EXT_V + extend_art[b * LL + l]] = 0.f;
        }
        if (tid < 32) toks[tid] = abstract[tid * TT + t];
        __syncthreads();
        for (int i = tid; i < 8192; i += 256) {   // emb
            int b = i >> 8, k = i & 255;
            xs[k * 33 + b] = emb[(size_t)toks[b] * 256 + k];
        }
        for (int i = tid; i < 8192; i += 256) {   // prev dec_out
            int b = i >> 8, k = i & 255;
            xs[(256 + k) * 33 + b] = g_pout[b * 256 + k];
        }
        for (int i = tid; i < 8192; i += 256) {   // h0 prev ([j][b] layout)
            int k = i >> 5, b = i & 31;
            xs[(512 + k) * 33 + b] = g_h0T[p][i];
        }
    } else {
        for (int i = tid; i < 8192; i += 256) {   // h0 new
            int k = i >> 5, b = i & 31;
            xs[k * 33 + b] = g_h0T[p ^ 1][i];
        }
        for (int i = tid; i < 8192; i += 256) {   // h1 prev
            int k = i >> 5, b = i & 31;
            xs[(256 + k) * 33 + b] = g_h1T[p][i];
        }
    }
    __syncthreads();

    const int w = tid >> 5, lane = tid & 31;
    const int u = w & 1, q = w >> 1;
    const int jrow = blockIdx.x * 2 + u;
    const float* W = (LAYER == 0) ? g_Wcat0 : g_Wcat1;

    const float4* wr[4];
    #pragma unroll
    for (int g = 0; g < 4; g++)
        wr[g] = (const float4*)(W + ((size_t)(g * 256 + jrow)) * K) + q * (KQ / 4);
    const float* xq = xs + (q * KQ) * 33 + lane;

    float a[4] = {0.f, 0.f, 0.f, 0.f};
    #pragma unroll 2
    for (int k4 = 0; k4 < KQ / 4; k4++) {
        float x0 = xq[(4 * k4 + 0) * 33], x1 = xq[(4 * k4 + 1) * 33];
        float x2 = xq[(4 * k4 + 2) * 33], x3 = xq[(4 * k4 + 3) * 33];
        #pragma unroll
        for (int g = 0; g < 4; g++) {
            float4 wv = wr[g][k4];
            a[g] = fmaf(wv.x, x0, fmaf(wv.y, x1, fmaf(wv.z, x2, fmaf(wv.w, x3, a[g]))));
        }
    }
    #pragma unroll
    for (int g = 0; g < 4; g++) part[g][u][q][lane] = a[g];
    __syncthreads();

    if (tid < 64) {
        int uu = tid >> 5, b = tid & 31;
        int jj = blockIdx.x * 2 + uu;
        const float* bs = (LAYER == 0) ? g_bsum0 : g_bsum1;
        float gv[4];
        #pragma unroll
        for (int g = 0; g < 4; g++)
            gv[g] = part[g][uu][0][b] + part[g][uu][1][b] + part[g][uu][2][b] +
                    part[g][uu][3][b] + bs[g * 256 + jj];
        float* cptr = (LAYER == 0) ? g_c0 : g_c1;
        float cv = cptr[jj * 32 + b];
        float c2 = sigf(gv[1]) * cv + sigf(gv[0]) * tanhf(gv[2]);
        float h2 = sigf(gv[3]) * tanhf(c2);
        cptr[jj * 32 + b] = c2;
        float* hout = (LAYER == 0) ? g_h0T[p ^ 1] : g_h1T[p ^ 1];
        hout[jj * 32 + b] = h2;
    }
}

// ---------------- attention + proj + copy gate + scatter (1 block per batch) ----------------
// mask read as int32 nonzero-test (bool coerced by harness; float32 1.0f also nonzero).
__global__ void __launch_bounds__(256) kAtt(
        const float* __restrict__ enc_mem, const float* __restrict__ enc_proj,
        const int* __restrict__ mask, const int* __restrict__ extend_art,
        const float* __restrict__ attn_w, const float* __restrict__ projW,
        const float* __restrict__ projb,
        const float* __restrict__ v_c, const float* __restrict__ v_s,
        const float* __restrict__ v_i, const float* __restrict__ copy_b,
        const float* __restrict__ emb, const int* __restrict__ abstract, int t) {
    __shared__ float ls[256], qs[256], as_[LL], red[256];
    __shared__ float s_gate;
    const int b = blockIdx.x, tid = threadIdx.x;
    const int pr = (t & 1) ^ 1;

    ls[tid] = g_h1T[pr][tid * 32 + b];
    if (tid == 0) g_sum[b] = 0.f;      // zero for kLogitsOut of this step
    __syncthreads();

    // query = lstm_out @ attn_w
    {
        float q0 = 0, q1 = 0, q2 = 0, q3 = 0;
        #pragma unroll 4
        for (int k = 0; k < 256; k += 4) {
            q0 = fmaf(ls[k + 0], attn_w[(k + 0) * 256 + tid], q0);
            q1 = fmaf(ls[k + 1], attn_w[(k + 1) * 256 + tid], q1);
            q2 = fmaf(ls[k + 2], attn_w[(k + 2) * 256 + tid], q2);
            q3 = fmaf(ls[k + 3], attn_w[(k + 3) * 256 + tid], q3);
        }
        qs[tid] = (q0 + q1) + (q2 + q3);
    }
    __syncthreads();

    // masked scores; small magnitudes -> max-free softmax is safe
    int anym = 0;
    for (int l = tid; l < LL; l += 256) {
        const float4* ep = (const float4*)(enc_proj + ((size_t)b * LL + l) * 256);
        float s0 = 0, s1 = 0;
        #pragma unroll 8
        for (int k4 = 0; k4 < 64; k4++) {
            float4 e = ep[k4];
            s0 = fmaf(qs[k4 * 4 + 0], e.x, fmaf(qs[k4 * 4 + 1], e.y, s0));
            s1 = fmaf(qs[k4 * 4 + 2], e.z, fmaf(qs[k4 * 4 + 3], e.w, s1));
        }
        int m = (mask[b * LL + l] != 0);
        anym |= m;
        as_[l] = m ? (s0 + s1) : -1e18f;
    }
    int any = __syncthreads_or(anym);

    float ps = 0.f;
    for (int l = tid; l < LL; l += 256) {
        float e = any ? __expf(as_[l]) : 1.0f;   // all-masked -> uniform
        as_[l] = e;
        ps += e;
    }
    red[tid] = ps; __syncthreads();
    for (int s = 128; s > 0; s >>= 1) { if (tid < s) red[tid] += red[tid + s]; __syncthreads(); }
    float inv = 1.0f / red[0];
    __syncthreads();
    for (int l = tid; l < LL; l += 256) as_[l] *= inv;
    __syncthreads();

    // ctx
    {
        float c0a = 0, c1a = 0, c2a = 0, c3a = 0;
        const float* em = enc_mem + (size_t)b * LL * 256 + tid;
        #pragma unroll 4
        for (int l = 0; l < LL; l += 4) {
            c0a = fmaf(as_[l + 0], em[(size_t)(l + 0) * 256], c0a);
            c1a = fmaf(as_[l + 1], em[(size_t)(l + 1) * 256], c1a);
            c2a = fmaf(as_[l + 2], em[(size_t)(l + 2) * 256], c2a);
            c3a = fmaf(as_[l + 3], em[(size_t)(l + 3) * 256], c3a);
        }
        __syncthreads();              // everyone done reading qs (query)
        qs[tid] = (c0a + c1a) + (c2a + c3a);   // qs now holds ctx
    }
    __syncthreads();

    // dec_out = [ls | ctx] @ projW^T + projb
    {
        const float4* pw = (const float4*)(projW + (size_t)tid * 512);
        float d0 = projb[tid], d1 = 0.f;
        #pragma unroll 8
        for (int k4 = 0; k4 < 64; k4++) {
            float4 wv = pw[k4];
            d0 = fmaf(ls[k4 * 4 + 0], wv.x, fmaf(ls[k4 * 4 + 1], wv.y, d0));
            d1 = fmaf(ls[k4 * 4 + 2], wv.z, fmaf(ls[k4 * 4 + 3], wv.w, d1));
        }
        #pragma unroll 8
        for (int k4 = 64; k4 < 128; k4++) {
            float4 wv = pw[k4];
            int k = (k4 - 64) * 4;
            d0 = fmaf(qs[k + 0], wv.x, fmaf(qs[k + 1], wv.y, d0));
            d1 = fmaf(qs[k + 2], wv.z, fmaf(qs[k + 3], wv.w, d1));
        }
        g_pout[b * 256 + tid] = d0 + d1;
    }

    // copy gate
    {
        int tok = abstract[b * TT + t];
        float gp = qs[tid] * v_c[tid] + ls[tid] * v_s[tid] + emb[(size_t)tok * 256 + tid] * v_i[tid];
        red[tid] = gp; __syncthreads();
        for (int s = 128; s > 0; s >>= 1) { if (tid < s) red[tid] += red[tid + s]; __syncthreads(); }
        if (tid == 0) {
            float g = sigf(red[0] + copy_b[0]);
            s_gate = g;
            g_gate[b] = g;
        }
        __syncthreads();
    }

    // copy scatter (g_add zeroed by kGates<0> of this step)
    float gg = s_gate;
    for (int l = tid; l < LL; l += 256)
        atomicAdd(&g_add[b * EXT_V + extend_art[b * LL + l]], as_[l] * gg);
}

// ---------------- logits GEMM + exp + sums + grid-sync + final log-prob write ----------------
// grid NBLK=148 (one block per SM, all wave-1 resident -> spin is safe), block 256.
__global__ void __launch_bounds__(256) kLogitsOut(
        const float* __restrict__ emb, float* __restrict__ out, int t) {
    __shared__ u64 decp[32 * 128];   // dec packed k-pairs, [b][kp]
    __shared__ float ssum[32];
    __shared__ float sscale[32];
    const int tid = threadIdx.x;

    for (int i = tid; i < 4096; i += 256) {
        int b = i >> 7, kp = i & 127;
        decp[i] = *(const u64*)(g_pout + b * 256 + kp * 2);
    }
    if (tid < 32) ssum[tid] = 0.f;
    __syncthreads();

    const int vg = tid & 15, bg = tid >> 4;
    const int b0 = bg * 2;
    const u64* d0 = decp + b0 * 128;
    const u64* d1 = decp + (b0 + 1) * 128;
    const int v0 = (int)((long long)blockIdx.x * VV / NBLK);
    const int v1 = (int)((long long)(blockIdx.x + 1) * VV / NBLK);

    float ts0 = 0.f, ts1 = 0.f;
    for (int vb = v0; vb < v1; vb += 64) {
        int va = vb + vg;
        const ulonglong2* er[4];
        #pragma unroll
        for (int i = 0; i < 4; i++) {
            int v = va + i * 16; if (v > VV - 1) v = VV - 1;
            er[i] = (const ulonglong2*)(emb + (size_t)v * 256);
        }
        u64 acc[4][2];
        #pragma unroll
        for (int i = 0; i < 4; i++) { acc[i][0] = 0ull; acc[i][1] = 0ull; }

        #pragma unroll 4
        for (int k4 = 0; k4 < 64; k4++) {
            u64 da = d0[2 * k4], db = d0[2 * k4 + 1];
            u64 dc = d1[2 * k4], dd = d1[2 * k4 + 1];
            #pragma unroll
            for (int i = 0; i < 4; i++) {
                ulonglong2 wv = er[i][k4];
                acc[i][0] = ffma2(wv.x, da, acc[i][0]);
                acc[i][0] = ffma2(wv.y, db, acc[i][0]);
                acc[i][1] = ffma2(wv.x, dc, acc[i][1]);
                acc[i][1] = ffma2(wv.y, dd, acc[i][1]);
            }
        }
        #pragma unroll
        for (int i = 0; i < 4; i++) {
            int v = va + i * 16;
            if (v < v1) {
                float p0 = __expf(sum2(acc[i][0]));
                float p1 = __expf(sum2(acc[i][1]));
                g_scr[(size_t)b0 * VV + v] = p0;
                g_scr[(size_t)(b0 + 1) * VV + v] = p1;
                ts0 += p0; ts1 += p1;
            }
        }
    }
    atomicAdd(&ssum[b0], ts0);
    atomicAdd(&ssum[b0 + 1], ts1);
    __syncthreads();
    if (tid < 32) atomicAdd(&g_sum[tid], ssum[tid]);

    // ---- grid-wide sync: all 148 blocks posted their partial sums ----
    __threadfence();
    if (tid == 0) {
        atomicAdd(&g_cnt, 1u);
        const unsigned target = (unsigned)NBLK * (unsigned)(t + 1);
        while (*((volatile unsigned*)&g_cnt) < target) { __nanosleep(64); }
    }
    __syncthreads();
    __threadfence();

    if (tid < 32) sscale[tid] = (1.0f - g_gate[tid]) / g_sum[tid];
    __syncthreads();

    // ---- final output for this block's v-range, all batches ----
    for (int b = 0; b < BB; b++) {
        float scale = sscale[b];
        const float* sc = g_scr + (size_t)b * VV;
        const float* ad = g_add + (size_t)b * EXT_V;
        float* ob = out + ((size_t)b * TT + t) * EXT_V;
        for (int v = v0 + tid; v < v1; v += 256)
            ob[v] = __logf(sc[v] * scale + ad[v] + 1e-12f);
    }
    // pad region v in [VV, EXT_V): gen term is exactly 0 (matches -1e8 pad underflow)
    if (blockIdx.x < EXT_V - VV && tid < BB) {
        int vp = VV + blockIdx.x;
        out[((size_t)tid * TT + t) * EXT_V + vp] = __logf(g_add[(size_t)tid * EXT_V + vp] + 1e-12f);
    }
}

// ---------------- launch ----------------
extern "C" void kernel_launch(void* const* d_in, const int* in_sizes, int n_in,
                              void* d_out, int out_size) {
    const int S = (n_in >= 25) ? 1 : 0;   // extend_vsize scalar present or not
    const int* abstract        = (const int*)d_in[0];
    const float* enc_mem       = (const float*)d_in[1];
    const float* enc_proj      = (const float*)d_in[2];
    const int* mask            = (const int*)d_in[3];
    const int* extend_art      = (const int*)d_in[4];
    const float* h0            = (const float*)d_in[5 + S];
    const float* c0            = (const float*)d_in[6 + S];
    const float* pout          = (const float*)d_in[7 + S];
    const float* emb           = (const float*)d_in[8 + S];
    const float* Wih0          = (const float*)d_in[9 + S];
    const float* Whh0          = (const float*)d_in[10 + S];
    const float* bih0          = (const float*)d_in[11 + S];
    const float* bhh0          = (const float*)d_in[12 + S];
    const float* Wih1          = (const float*)d_in[13 + S];
    const float* Whh1          = (const float*)d_in[14 + S];
    const float* bih1          = (const float*)d_in[15 + S];
    const float* bhh1          = (const float*)d_in[16 + S];
    const float* attn_w        = (const float*)d_in[17 + S];
    const float* projW         = (const float*)d_in[18 + S];
    const float* projb         = (const float*)d_in[19 + S];
    const float* v_c           = (const float*)d_in[20 + S];
    const float* v_s           = (const float*)d_in[21 + S];
    const float* v_i           = (const float*)d_in[22 + S];
    const float* copy_b        = (const float*)d_in[23 + S];
    float* out = (float*)d_out;

    cudaFuncSetAttribute(kGates<0>, cudaFuncAttributeMaxDynamicSharedMemorySize, 768 * 33 * 4);
    cudaFuncSetAttribute(kGates<1>, cudaFuncAttributeMaxDynamicSharedMemorySize, 512 * 33 * 4);

    kPrep<<<5128, 256>>>(Wih0, Whh0, bih0, bhh0, Wih1, Whh1, bih1, bhh1);
    kInit<<<32, 256>>>(h0, c0, pout);
    for (int t = 0; t < TT; t++) {
        kGates<0><<<128, 256, 768 * 33 * 4>>>(emb, abstract, extend_art, t);
        kGates<1><<<128, 256, 512 * 33 * 4>>>(emb, abstract, extend_art, t);
        kAtt<<<32, 256>>>(enc_mem, enc_proj, mask, extend_art, attn_w, projW, projb,
                          v_c, v_s, v_i, copy_b, emb, abstract, t);
        kLogitsOut<<<NBLK, 256>>>(emb, out, t);
    }
}

// round 14
// speedup vs baseline: 1.8462x; 1.8462x over previous
#include <cuda_runtime.h>
#include <cuda_bf16.h>
#include <cstdint>

#define BB 32
#define TT 48
#define LL 400
#define VV 32000
#define EXT_V 32050
#define NBLK 148
#define PITCH 66   // words per 64-float semb row (64 data + 2 pad); even (8B align), bank-stride 2

typedef unsigned long long u64;

// ---------------- persistent device state ----------------
__device__ float g_Wcat0[1024 * 768];   // [Wih0 | Whh0]
__device__ float g_Wcat1[1024 * 512];   // [Wih1 | Whh1]
__device__ float g_bsum0[1024];
__device__ float g_bsum1[1024];
__device__ float g_h0T[2][8192];        // [parity][j*32+b]
__device__ float g_h1T[2][8192];
__device__ float g_c0[8192];            // [j*32+b], in-place
__device__ float g_c1[8192];
__device__ float g_pout[8192];          // dec_out / prev_out, [b*256+e]
__device__ float g_gate[BB];
__device__ float g_sum[BB];
__device__ unsigned g_cnt;              // arrival counter (reset each replay in kInit)
__device__ float g_scr[BB * VV];        // exp(logits), [b][v]
__device__ float g_add[BB * EXT_V];     // copy-scatter buffer

__device__ __forceinline__ float sigf(float x) { return 1.0f / (1.0f + __expf(-x)); }

__device__ __forceinline__ u64 ffma2(u64 a, u64 b, u64 c) {
    u64 r;
    asm("fma.rn.f32x2 %0, %1, %2, %3;" : "=l"(r) : "l"(a), "l"(b), "l"(c));
    return r;
}
__device__ __forceinline__ float sum2(u64 v) {
    float a, b;
    asm("mov.b64 {%0, %1}, %2;" : "=f"(a), "=f"(b) : "l"(v));
    return a + b;
}

// ---------------- prep: concat weights, sum biases ----------------
__global__ void __launch_bounds__(256) kPrep(
        const float* __restrict__ Wih0, const float* __restrict__ Whh0,
        const float* __restrict__ bih0, const float* __restrict__ bhh0,
        const float* __restrict__ Wih1, const float* __restrict__ Whh1,
        const float* __restrict__ bih1, const float* __restrict__ bhh1) {
    int i = blockIdx.x * 256 + threadIdx.x;
    if (i < 1024 * 768) {
        int r = i / 768, k = i - r * 768;
        g_Wcat0[i] = (k < 512) ? Wih0[r * 512 + k] : Whh0[r * 256 + (k - 512)];
        return;
    }
    int j = i - 1024 * 768;
    if (j < 1024 * 512) {
        int r = j / 512, k = j - r * 512;
        g_Wcat1[j] = (k < 256) ? Wih1[r * 256 + k] : Whh1[r * 256 + (k - 256)];
        return;
    }
    int m = j - 1024 * 512;
    if (m < 1024) g_bsum0[m] = bih0[m] + bhh0[m];
    else if (m < 2048) g_bsum1[m - 1024] = bih1[m - 1024] + bhh1[m - 1024];
}

// ---------------- init state (every replay) ----------------
__global__ void __launch_bounds__(256) kInit(
        const float* __restrict__ h0, const float* __restrict__ c0,
        const float* __restrict__ pout) {
    int i = blockIdx.x * 256 + threadIdx.x;   // i = b*256 + j
    if (i == 0) g_cnt = 0u;
    if (i >= 8192) return;
    int b = i >> 8, j = i & 255;
    g_h0T[0][j * 32 + b] = h0[i];
    g_h1T[0][j * 32 + b] = h0[8192 + i];
    g_c0[j * 32 + b] = c0[i];
    g_c1[j * 32 + b] = c0[8192 + i];
    g_pout[i] = pout[i];
}

// ---------------- LSTM gates + activations (layer 0 or 1) ----------------
// grid 128, block 256. Block owns units j0=blk*2, j0+1. warp w: u=w&1 (unit),
// q=w>>1 (K-quarter). Fills are float4-vectorized (8 independent loads/thread).
template<int LAYER>
__global__ void __launch_bounds__(256) kGates(
        const float* __restrict__ emb, const int* __restrict__ abstract,
        const int* __restrict__ extend_art, int t) {
    constexpr int K = (LAYER == 0) ? 768 : 512;
    constexpr int KQ = K / 4;
    extern __shared__ float xs[];                 // [K][33]
    __shared__ float part[4][2][4][32];           // [gate][unit][quarter][batch]
    __shared__ int toks[32];
    const int tid = threadIdx.x;
    const int p = t & 1;

    if (LAYER == 0) {
        // zero copy-scatter targets for this step (positions are static per batch)
        int gid = blockIdx.x * 256 + tid;
        if (gid < BB * LL) {
            int b = gid / LL, l = gid - b * LL;
            g_add[b * EXT_V + extend_art[b * LL + l]] = 0.f;
        }
        if (tid < 32) toks[tid] = abstract[tid * TT + t];
        __syncthreads();
        #pragma unroll
        for (int it = 0; it < 8; it++) {          // emb rows, float4 along k
            int i = it * 256 + tid;
            int b = i >> 6, q = i & 63;
            float4 v = *(const float4*)(emb + (size_t)toks[b] * 256 + q * 4);
            float* d = xs + (4 * q) * 33 + b;
            d[0] = v.x; d[33] = v.y; d[66] = v.z; d[99] = v.w;
        }
        #pragma unroll
        for (int it = 0; it < 8; it++) {          // prev dec_out
            int i = it * 256 + tid;
            int b = i >> 6, q = i & 63;
            float4 v = *(const float4*)(g_pout + b * 256 + q * 4);
            float* d = xs + (256 + 4 * q) * 33 + b;
            d[0] = v.x; d[33] = v.y; d[66] = v.z; d[99] = v.w;
        }
        #pragma unroll
        for (int it = 0; it < 8; it++) {          // h0 prev ([j][b] layout, float4 over b)
            int i = it * 256 + tid;
            int k = i >> 3, b4 = (i & 7) * 4;
            float4 v = *(const float4*)(g_h0T[p] + k * 32 + b4);
            float* d = xs + (512 + k) * 33 + b4;
            d[0] = v.x; d[1] = v.y; d[2] = v.z; d[3] = v.w;
        }
    } else {
        #pragma unroll
        for (int it = 0; it < 8; it++) {          // h0 new
            int i = it * 256 + tid;
            int k = i >> 3, b4 = (i & 7) * 4;
            float4 v = *(const float4*)(g_h0T[p ^ 1] + k * 32 + b4);
            float* d = xs + k * 33 + b4;
            d[0] = v.x; d[1] = v.y; d[2] = v.z; d[3] = v.w;
        }
        #pragma unroll
        for (int it = 0; it < 8; it++) {          // h1 prev
            int i = it * 256 + tid;
            int k = i >> 3, b4 = (i & 7) * 4;
            float4 v = *(const float4*)(g_h1T[p] + k * 32 + b4);
            float* d = xs + (256 + k) * 33 + b4;
            d[0] = v.x; d[1] = v.y; d[2] = v.z; d[3] = v.w;
        }
    }
    __syncthreads();

    const int w = tid >> 5, lane = tid & 31;
    const int u = w & 1, q = w >> 1;
    const int jrow = blockIdx.x * 2 + u;
    const float* W = (LAYER == 0) ? g_Wcat0 : g_Wcat1;

    const float4* wr[4];
    #pragma unroll
    for (int g = 0; g < 4; g++)
        wr[g] = (const float4*)(W + ((size_t)(g * 256 + jrow)) * K) + q * (KQ / 4);
    const float* xq = xs + (q * KQ) * 33 + lane;

    float a[4] = {0.f, 0.f, 0.f, 0.f};
    #pragma unroll 4
    for (int k4 = 0; k4 < KQ / 4; k4++) {
        float x0 = xq[(4 * k4 + 0) * 33], x1 = xq[(4 * k4 + 1) * 33];
        float x2 = xq[(4 * k4 + 2) * 33], x3 = xq[(4 * k4 + 3) * 33];
        #pragma unroll
        for (int g = 0; g < 4; g++) {
            float4 wv = wr[g][k4];
            a[g] = fmaf(wv.x, x0, fmaf(wv.y, x1, fmaf(wv.z, x2, fmaf(wv.w, x3, a[g]))));
        }
    }
    #pragma unroll
    for (int g = 0; g < 4; g++) part[g][u][q][lane] = a[g];
    __syncthreads();

    if (tid < 64) {
        int uu = tid >> 5, b = tid & 31;
        int jj = blockIdx.x * 2 + uu;
        const float* bs = (LAYER == 0) ? g_bsum0 : g_bsum1;
        float gv[4];
        #pragma unroll
        for (int g = 0; g < 4; g++)
            gv[g] = part[g][uu][0][b] + part[g][uu][1][b] + part[g][uu][2][b] +
                    part[g][uu][3][b] + bs[g * 256 + jj];
        float* cptr = (LAYER == 0) ? g_c0 : g_c1;
        float cv = cptr[jj * 32 + b];
        float c2 = sigf(gv[1]) * cv + sigf(gv[0]) * tanhf(gv[2]);
        float h2 = sigf(gv[3]) * tanhf(c2);
        cptr[jj * 32 + b] = c2;
        float* hout = (LAYER == 0) ? g_h0T[p ^ 1] : g_h1T[p ^ 1];
        hout[jj * 32 + b] = h2;
    }
}

// ---------------- attention + proj + copy gate + scatter (1 block per batch) ----------------
__global__ void __launch_bounds__(256) kAtt(
        const float* __restrict__ enc_mem, const float* __restrict__ enc_proj,
        const int* __restrict__ mask, const int* __restrict__ extend_art,
        const float* __restrict__ attn_w, const float* __restrict__ projW,
        const float* __restrict__ projb,
        const float* __restrict__ v_c, const float* __restrict__ v_s,
        const float* __restrict__ v_i, const float* __restrict__ copy_b,
        const float* __restrict__ emb, const int* __restrict__ abstract, int t) {
    __shared__ float ls[256], qs[256], as_[LL], red[256];
    __shared__ float s_gate;
    const int b = blockIdx.x, tid = threadIdx.x;
    const int pr = (t & 1) ^ 1;

    ls[tid] = g_h1T[pr][tid * 32 + b];
    if (tid == 0) g_sum[b] = 0.f;      // zero for kLogitsOut of this step
    __syncthreads();

    // query = lstm_out @ attn_w   (8 accumulators -> deep MLP)
    {
        float qa[8] = {0, 0, 0, 0, 0, 0, 0, 0};
        #pragma unroll 2
        for (int k = 0; k < 256; k += 8) {
            #pragma unroll
            for (int j = 0; j < 8; j++)
                qa[j] = fmaf(ls[k + j], attn_w[(k + j) * 256 + tid], qa[j]);
        }
        qs[tid] = ((qa[0] + qa[1]) + (qa[2] + qa[3])) + ((qa[4] + qa[5]) + (qa[6] + qa[7]));
    }
    __syncthreads();

    // masked scores; small magnitudes -> max-free softmax is safe
    int anym = 0;
    for (int l = tid; l < LL; l += 256) {
        const float4* ep = (const float4*)(enc_proj + ((size_t)b * LL + l) * 256);
        float s0 = 0, s1 = 0;
        #pragma unroll 8
        for (int k4 = 0; k4 < 64; k4++) {
            float4 e = ep[k4];
            s0 = fmaf(qs[k4 * 4 + 0], e.x, fmaf(qs[k4 * 4 + 1], e.y, s0));
            s1 = fmaf(qs[k4 * 4 + 2], e.z, fmaf(qs[k4 * 4 + 3], e.w, s1));
        }
        int m = (mask[b * LL + l] != 0);
        anym |= m;
        as_[l] = m ? (s0 + s1) : -1e18f;
    }
    int any = __syncthreads_or(anym);

    float ps = 0.f;
    for (int l = tid; l < LL; l += 256) {
        float e = any ? __expf(as_[l]) : 1.0f;   // all-masked -> uniform
        as_[l] = e;
        ps += e;
    }
    red[tid] = ps; __syncthreads();
    for (int s = 128; s > 0; s >>= 1) { if (tid < s) red[tid] += red[tid + s]; __syncthreads(); }
    float inv = 1.0f / red[0];
    __syncthreads();
    for (int l = tid; l < LL; l += 256) as_[l] *= inv;
    __syncthreads();

    // ctx   (8 accumulators, 400 = 50*8)
    {
        float ca[8] = {0, 0, 0, 0, 0, 0, 0, 0};
        const float* em = enc_mem + (size_t)b * LL * 256 + tid;
        #pragma unroll 2
        for (int l = 0; l < LL; l += 8) {
            #pragma unroll
            for (int j = 0; j < 8; j++)
                ca[j] = fmaf(as_[l + j], em[(size_t)(l + j) * 256], ca[j]);
        }
        __syncthreads();              // everyone done reading qs (query)
        qs[tid] = ((ca[0] + ca[1]) + (ca[2] + ca[3])) + ((ca[4] + ca[5]) + (ca[6] + ca[7]));
    }
    __syncthreads();

    // dec_out = [ls | ctx] @ projW^T + projb
    {
        const float4* pw = (const float4*)(projW + (size_t)tid * 512);
        float d0 = projb[tid], d1 = 0.f;
        #pragma unroll 8
        for (int k4 = 0; k4 < 64; k4++) {
            float4 wv = pw[k4];
            d0 = fmaf(ls[k4 * 4 + 0], wv.x, fmaf(ls[k4 * 4 + 1], wv.y, d0));
            d1 = fmaf(ls[k4 * 4 + 2], wv.z, fmaf(ls[k4 * 4 + 3], wv.w, d1));
        }
        #pragma unroll 8
        for (int k4 = 64; k4 < 128; k4++) {
            float4 wv = pw[k4];
            int k = (k4 - 64) * 4;
            d0 = fmaf(qs[k + 0], wv.x, fmaf(qs[k + 1], wv.y, d0));
            d1 = fmaf(qs[k + 2], wv.z, fmaf(qs[k + 3], wv.w, d1));
        }
        g_pout[b * 256 + tid] = d0 + d1;
    }

    // copy gate
    {
        int tok = abstract[b * TT + t];
        float gp = qs[tid] * v_c[tid] + ls[tid] * v_s[tid] + emb[(size_t)tok * 256 + tid] * v_i[tid];
        red[tid] = gp; __syncthreads();
        for (int s = 128; s > 0; s >>= 1) { if (tid < s) red[tid] += red[tid + s]; __syncthreads(); }
        if (tid == 0) {
            float g = sigf(red[0] + copy_b[0]);
            s_gate = g;
            g_gate[b] = g;
        }
        __syncthreads();
    }

    // copy scatter (g_add zeroed by kGates<0> of this step)
    float gg = s_gate;
    for (int l = tid; l < LL; l += 256)
        atomicAdd(&g_add[b * EXT_V + extend_art[b * LL + l]], as_[l] * gg);
}

// ---------------- logits GEMM (smem-tiled) + exp + sums + grid-sync + output ----------------
// grid NBLK=148 (all wave-1 resident -> spin safe), block 256.
// Tile: 128 v-rows x 32 b, k in 4 chunks of 64. warp = 4 batches (uniform dec loads),
// lane = 4 v-rows (interleaved stride 32, conflict-free via PITCH=66). emb read once/block.
__global__ void __launch_bounds__(256) kLogitsOut(
        const float* __restrict__ emb, float* __restrict__ out, int t) {
    extern __shared__ char dyn[];
    float* semb = (float*)dyn;                          // 128*PITCH floats = 33792B
    u64* sdec   = (u64*)(dyn + 128 * PITCH * 4);        // 32*128 u64 = 32768B
    float* ssum = (float*)(dyn + 128 * PITCH * 4 + 32768);   // 32 floats
    float* sscale = ssum + 32;                               // 32 floats
    const int tid = threadIdx.x;

    for (int i = tid; i < 4096; i += 256)               // dec packed k-pairs, [b][kp]
        sdec[i] = *(const u64*)(g_pout + (i >> 7) * 256 + (i & 127) * 2);
    if (tid < 32) ssum[tid] = 0.f;

    const int tb = tid >> 5;            // warp -> batches 4tb..4tb+3
    const int tv = tid & 31;            // lane -> v rows tv+32j
    const int v0 = (int)((long long)blockIdx.x * VV / NBLK);
    const int v1 = (int)((long long)(blockIdx.x + 1) * VV / NBLK);

    float lsum[4] = {0.f, 0.f, 0.f, 0.f};

    for (int vt = v0; vt < v1; vt += 128) {
        u64 acc[4][4];                  // [j: v][i: b]
        #pragma unroll
        for (int j = 0; j < 4; j++)
            #pragma unroll
            for (int i = 0; i < 4; i++) acc[j][i] = 0ull;

        for (int kc = 0; kc < 4; kc++) {
            __syncthreads();            // prior reads of semb done
            #pragma unroll
            for (int it = 0; it < 8; it++) {   // fill 128 rows x 64 floats, coalesced
                int i = it * 256 + tid;
                int r = i >> 4, qq = i & 15;
                int vr = vt + r; if (vr > VV - 1) vr = VV - 1;
                float4 v = *(const float4*)(emb + (size_t)vr * 256 + kc * 64 + qq * 4);
                float* d = semb + r * PITCH + qq * 4;
                d[0] = v.x; d[1] = v.y; d[2] = v.z; d[3] = v.w;
            }
            __syncthreads();
            const u64* dp = sdec + (tb * 4) * 128 + kc * 32;
            #pragma unroll 2
            for (int kp = 0; kp < 32; kp++) {
                u64 d0 = dp[kp], d1 = dp[128 + kp], d2 = dp[256 + kp], d3 = dp[384 + kp];
                #pragma unroll
                for (int j = 0; j < 4; j++) {
                    u64 e = *(const u64*)(semb + (tv + 32 * j) * PITCH + kp * 2);
                    acc[j][0] = ffma2(e, d0, acc[j][0]);
                    acc[j][1] = ffma2(e, d1, acc[j][1]);
                    acc[j][2] = ffma2(e, d2, acc[j][2]);
                    acc[j][3] = ffma2(e, d3, acc[j][3]);
                }
            }
        }
        #pragma unroll
        for (int j = 0; j < 4; j++) {
            int v = vt + tv + 32 * j;
            if (v < v1) {
                #pragma unroll
                for (int i = 0; i < 4; i++) {
                    float pz = __expf(sum2(acc[j][i]));
                    g_scr[(size_t)(4 * tb + i) * VV + v] = pz;
                    lsum[i] += pz;
                }
            }
        }
    }
    // per-warp reduce (all lanes of a warp share the same 4 batches)
    #pragma unroll
    for (int i = 0; i < 4; i++) {
        float v = lsum[i];
        #pragma unroll
        for (int o = 16; o > 0; o >>= 1) v += __shfl_xor_sync(0xffffffffu, v, o);
        if (tv == 0) atomicAdd(&ssum[4 * tb + i], v);
    }
    __syncthreads();
    if (tid < 32) atomicAdd(&g_sum[tid], ssum[tid]);

    // ---- grid-wide sync: all 148 blocks posted their partial sums ----
    __threadfence();
    if (tid == 0) {
        atomicAdd(&g_cnt, 1u);
        const unsigned target = (unsigned)NBLK * (unsigned)(t + 1);
        while (*((volatile unsigned*)&g_cnt) < target) { __nanosleep(64); }
    }
    __syncthreads();
    __threadfence();

    if (tid < 32) sscale[tid] = (1.0f - g_gate[tid]) / g_sum[tid];
    __syncthreads();

    // ---- final output for this block's v-range, all batches ----
    for (int b = 0; b < BB; b++) {
        float scale = sscale[b];
        const float* sc = g_scr + (size_t)b * VV;
        const float* ad = g_add + (size_t)b * EXT_V;
        float* ob = out + ((size_t)b * TT + t) * EXT_V;
        for (int v = v0 + tid; v < v1; v += 256)
            ob[v] = __logf(sc[v] * scale + ad[v] + 1e-12f);
    }
    // pad region v in [VV, EXT_V): gen term is exactly 0 (matches -1e8 pad underflow)
    if (blockIdx.x < EXT_V - VV && tid < BB) {
        int vp = VV + blockIdx.x;
        out[((size_t)tid * TT + t) * EXT_V + vp] = __logf(g_add[(size_t)tid * EXT_V + vp] + 1e-12f);
    }
}

// ---------------- launch ----------------
extern "C" void kernel_launch(void* const* d_in, const int* in_sizes, int n_in,
                              void* d_out, int out_size) {
    const int S = (n_in >= 25) ? 1 : 0;   // extend_vsize scalar present or not
    const int* abstract        = (const int*)d_in[0];
    const float* enc_mem       = (const float*)d_in[1];
    const float* enc_proj      = (const float*)d_in[2];
    const int* mask            = (const int*)d_in[3];
    const int* extend_art      = (const int*)d_in[4];
    const float* h0            = (const float*)d_in[5 + S];
    const float* c0            = (const float*)d_in[6 + S];
    const float* pout          = (const float*)d_in[7 + S];
    const float* emb           = (const float*)d_in[8 + S];
    const float* Wih0          = (const float*)d_in[9 + S];
    const float* Whh0          = (const float*)d_in[10 + S];
    const float* bih0          = (const float*)d_in[11 + S];
    const float* bhh0          = (const float*)d_in[12 + S];
    const float* Wih1          = (const float*)d_in[13 + S];
    const float* Whh1          = (const float*)d_in[14 + S];
    const float* bih1          = (const float*)d_in[15 + S];
    const float* bhh1          = (const float*)d_in[16 + S];
    const float* attn_w        = (const float*)d_in[17 + S];
    const float* projW         = (const float*)d_in[18 + S];
    const float* projb         = (const float*)d_in[19 + S];
    const float* v_c           = (const float*)d_in[20 + S];
    const float* v_s           = (const float*)d_in[21 + S];
    const float* v_i           = (const float*)d_in[22 + S];
    const float* copy_b        = (const float*)d_in[23 + S];
    float* out = (float*)d_out;

    const int smemL = 128 * PITCH * 4 + 32768 + 64 * 4;   // semb + sdec + ssum/sscale
    cudaFuncSetAttribute(kGates<0>, cudaFuncAttributeMaxDynamicSharedMemorySize, 768 * 33 * 4);
    cudaFuncSetAttribute(kGates<1>, cudaFuncAttributeMaxDynamicSharedMemorySize, 512 * 33 * 4);
    cudaFuncSetAttribute(kLogitsOut, cudaFuncAttributeMaxDynamicSharedMemorySize, smemL);

    kPrep<<<5128, 256>>>(Wih0, Whh0, bih0, bhh0, Wih1, Whh1, bih1, bhh1);
    kInit<<<32, 256>>>(h0, c0, pout);
    for (int t = 0; t < TT; t++) {
        kGates<0><<<128, 256, 768 * 33 * 4>>>(emb, abstract, extend_art, t);
        kGates<1><<<128, 256, 512 * 33 * 4>>>(emb, abstract, extend_art, t);
        kAtt<<<32, 256>>>(enc_mem, enc_proj, mask, extend_art, attn_w, projW, projb,
                          v_c, v_s, v_i, copy_b, emb, abstract, t);
        kLogitsOut<<<NBLK, 256, smemL>>>(emb, out, t);
    }
}

// round 15
// speedup vs baseline: 2.1278x; 1.1525x over previous
#include <cuda_runtime.h>
#include <cuda_bf16.h>
#include <cstdint>

#define BB 32
#define TT 48
#define LL 400
#define VV 32000
#define EXT_V 32050
#define NBLK 148
#define GBLK 128
#define PITCH 66   // words per 64-float semb row; even (8B align), bank-stride 2

typedef unsigned long long u64;

// ---------------- persistent device state ----------------
__device__ float g_Wcat0[1024 * 768];   // [Wih0 | Whh0]
__device__ float g_Wcat1[1024 * 512];   // [Wih1 | Whh1]
__device__ float g_bsum0[1024];
__device__ float g_bsum1[1024];
__device__ float g_h0T[2][8192];        // [parity][j*32+b]
__device__ float g_h1T[2][8192];
__device__ float g_c0[8192];            // [j*32+b], in-place
__device__ float g_c1[8192];
__device__ float g_pout[8192];          // dec_out / prev_out, [b*256+e]
__device__ float g_gate[BB];
__device__ float g_sum[BB];
__device__ unsigned g_cnt;              // kLogitsOut arrival counter (reset each replay)
__device__ unsigned g_cnt2;             // kGatesFused arrival counter (reset each replay)
__device__ float g_scr[BB * VV];        // exp(logits), [b][v]
__device__ float g_add[BB * EXT_V];     // copy-scatter buffer

__device__ __forceinline__ float sigf(float x) { return 1.0f / (1.0f + __expf(-x)); }

__device__ __forceinline__ u64 ffma2(u64 a, u64 b, u64 c) {
    u64 r;
    asm("fma.rn.f32x2 %0, %1, %2, %3;" : "=l"(r) : "l"(a), "l"(b), "l"(c));
    return r;
}
__device__ __forceinline__ float sum2(u64 v) {
    float a, b;
    asm("mov.b64 {%0, %1}, %2;" : "=f"(a), "=f"(b) : "l"(v));
    return a + b;
}

// ---------------- prep: concat weights, sum biases ----------------
__global__ void __launch_bounds__(256) kPrep(
        const float* __restrict__ Wih0, const float* __restrict__ Whh0,
        const float* __restrict__ bih0, const float* __restrict__ bhh0,
        const float* __restrict__ Wih1, const float* __restrict__ Whh1,
        const float* __restrict__ bih1, const float* __restrict__ bhh1) {
    int i = blockIdx.x * 256 + threadIdx.x;
    if (i < 1024 * 768) {
        int r = i / 768, k = i - r * 768;
        g_Wcat0[i] = (k < 512) ? Wih0[r * 512 + k] : Whh0[r * 256 + (k - 512)];
        return;
    }
    int j = i - 1024 * 768;
    if (j < 1024 * 512) {
        int r = j / 512, k = j - r * 512;
        g_Wcat1[j] = (k < 256) ? Wih1[r * 256 + k] : Whh1[r * 256 + (k - 256)];
        return;
    }
    int m = j - 1024 * 512;
    if (m < 1024) g_bsum0[m] = bih0[m] + bhh0[m];
    else if (m < 2048) g_bsum1[m - 1024] = bih1[m - 1024] + bhh1[m - 1024];
}

// ---------------- init state (every replay) ----------------
__global__ void __launch_bounds__(256) kInit(
        const float* __restrict__ h0, const float* __restrict__ c0,
        const float* __restrict__ pout) {
    int i = blockIdx.x * 256 + threadIdx.x;   // i = b*256 + j
    if (i == 0) { g_cnt = 0u; g_cnt2 = 0u; }
    if (i >= 8192) return;
    int b = i >> 8, j = i & 255;
    g_h0T[0][j * 32 + b] = h0[i];
    g_h1T[0][j * 32 + b] = h0[8192 + i];
    g_c0[j * 32 + b] = c0[i];
    g_c1[j * 32 + b] = c0[8192 + i];
    g_pout[i] = pout[i];
}

// ---------------- fused LSTM layers 0+1 (gates + activations), grid-spin between ----------------
// grid GBLK=128, block 256, 1 block/SM (123KB smem) -> all wave-1 resident, spin safe.
// Block owns units j0=blk*2, j0+1 (both layers). Weights staged in smem (L1 is flushed
// per launch on sm_103a, so L2-latency weight reads in the FMA loop were the R14 stall).
__global__ void __launch_bounds__(256) kGatesFused(
        const float* __restrict__ emb, const int* __restrict__ abstract,
        const int* __restrict__ extend_art, int t) {
    extern __shared__ float xs[];                 // [768][33] = 25344 floats
    float4* sw4 = (float4*)(xs + 25344);          // 8 rows x 192 float4 (layer0) / 128 (layer1)
    __shared__ float part[4][2][4][32];           // [gate][unit][quarter][batch]
    __shared__ int toks[32];
    const int tid = threadIdx.x;
    const int p = t & 1;
    const int blk = blockIdx.x;
    const int w = tid >> 5, lane = tid & 31;
    const int u = w & 1, q = w >> 1;

    // ================= Phase A: layer 0 =================
    {
        int gid = blk * 256 + tid;                // zero copy-scatter targets (static positions)
        if (gid < BB * LL) {
            int b = gid / LL, l = gid - b * LL;
            g_add[b * EXT_V + extend_art[b * LL + l]] = 0.f;
        }
        if (tid < 32) toks[tid] = abstract[tid * TT + t];
        __syncthreads();
        #pragma unroll
        for (int it = 0; it < 8; it++) {          // emb rows, float4 along k
            int i = it * 256 + tid;
            int b = i >> 6, qq = i & 63;
            float4 v = *(const float4*)(emb + (size_t)toks[b] * 256 + qq * 4);
            float* d = xs + (4 * qq) * 33 + b;
            d[0] = v.x; d[33] = v.y; d[66] = v.z; d[99] = v.w;
        }
        #pragma unroll
        for (int it = 0; it < 8; it++) {          // prev dec_out
            int i = it * 256 + tid;
            int b = i >> 6, qq = i & 63;
            float4 v = *(const float4*)(g_pout + b * 256 + qq * 4);
            float* d = xs + (256 + 4 * qq) * 33 + b;
            d[0] = v.x; d[33] = v.y; d[66] = v.z; d[99] = v.w;
        }
        #pragma unroll
        for (int it = 0; it < 8; it++) {          // h0 prev ([j][b] layout)
            int i = it * 256 + tid;
            int k = i >> 3, b4 = (i & 7) * 4;
            float4 v = *(const float4*)(g_h0T[p] + k * 32 + b4);
            float* d = xs + (512 + k) * 33 + b4;
            d[0] = v.x; d[1] = v.y; d[2] = v.z; d[3] = v.w;
        }
        #pragma unroll
        for (int it = 0; it < 6; it++) {          // W rows: 8 x 768 floats = 1536 float4
            int i = it * 256 + tid;
            int r = i / 192, c = i - r * 192;     // r = g*2+u
            sw4[i] = ((const float4*)(g_Wcat0 + (size_t)((r >> 1) * 256 + blk * 2 + (r & 1)) * 768))[c];
        }
        __syncthreads();

        const float4* wr[4];
        #pragma unroll
        for (int g = 0; g < 4; g++) wr[g] = sw4 + (g * 2 + u) * 192 + q * 48;
        const float* xq = xs + (q * 192) * 33 + lane;

        float a[4] = {0.f, 0.f, 0.f, 0.f};
        #pragma unroll 4
        for (int k4 = 0; k4 < 48; k4++) {
            float x0 = xq[(4 * k4 + 0) * 33], x1 = xq[(4 * k4 + 1) * 33];
            float x2 = xq[(4 * k4 + 2) * 33], x3 = xq[(4 * k4 + 3) * 33];
            #pragma unroll
            for (int g = 0; g < 4; g++) {
                float4 wv = wr[g][k4];
                a[g] = fmaf(wv.x, x0, fmaf(wv.y, x1, fmaf(wv.z, x2, fmaf(wv.w, x3, a[g]))));
            }
        }
        #pragma unroll
        for (int g = 0; g < 4; g++) part[g][u][q][lane] = a[g];
        __syncthreads();

        if (tid < 64) {
            int uu = tid >> 5, b = tid & 31;
            int jj = blk * 2 + uu;
            float gv[4];
            #pragma unroll
            for (int g = 0; g < 4; g++)
                gv[g] = part[g][uu][0][b] + part[g][uu][1][b] + part[g][uu][2][b] +
                        part[g][uu][3][b] + g_bsum0[g * 256 + jj];
            float cv = g_c0[jj * 32 + b];
            float c2 = sigf(gv[1]) * cv + sigf(gv[0]) * tanhf(gv[2]);
            float h2 = sigf(gv[3]) * tanhf(c2);
            g_c0[jj * 32 + b] = c2;
            g_h0T[p ^ 1][jj * 32 + b] = h2;
        }
        __syncthreads();
    }

    // ---- grid spin: all blocks' h0-new visible before layer 1 reads it ----
    __threadfence();
    if (tid == 0) {
        atomicAdd(&g_cnt2, 1u);
        const unsigned target = (unsigned)GBLK * (unsigned)(t + 1);
        while (*((volatile unsigned*)&g_cnt2) < target) { __nanosleep(32); }
    }
    __syncthreads();
    __threadfence();

    // ================= Phase B: layer 1 =================
    {
        #pragma unroll
        for (int it = 0; it < 8; it++) {          // h0 new
            int i = it * 256 + tid;
            int k = i >> 3, b4 = (i & 7) * 4;
            float4 v = *(const float4*)(g_h0T[p ^ 1] + k * 32 + b4);
            float* d = xs + k * 33 + b4;
            d[0] = v.x; d[1] = v.y; d[2] = v.z; d[3] = v.w;
        }
        #pragma unroll
        for (int it = 0; it < 8; it++) {          // h1 prev
            int i = it * 256 + tid;
            int k = i >> 3, b4 = (i & 7) * 4;
            float4 v = *(const float4*)(g_h1T[p] + k * 32 + b4);
            float* d = xs + (256 + k) * 33 + b4;
            d[0] = v.x; d[1] = v.y; d[2] = v.z; d[3] = v.w;
        }
        #pragma unroll
        for (int it = 0; it < 4; it++) {          // W rows: 8 x 512 floats = 1024 float4
            int i = it * 256 + tid;
            int r = i >> 7, c = i & 127;
            sw4[i] = ((const float4*)(g_Wcat1 + (size_t)((r >> 1) * 256 + blk * 2 + (r & 1)) * 512))[c];
        }
        __syncthreads();

        const float4* wr[4];
        #pragma unroll
        for (int g = 0; g < 4; g++) wr[g] = sw4 + (g * 2 + u) * 128 + q * 32;
        const float* xq = xs + (q * 128) * 33 + lane;

        float a[4] = {0.f, 0.f, 0.f, 0.f};
        #pragma unroll 4
        for (int k4 = 0; k4 < 32; k4++) {
            float x0 = xq[(4 * k4 + 0) * 33], x1 = xq[(4 * k4 + 1) * 33];
            float x2 = xq[(4 * k4 + 2) * 33], x3 = xq[(4 * k4 + 3) * 33];
            #pragma unroll
            for (int g = 0; g < 4; g++) {
                float4 wv = wr[g][k4];
                a[g] = fmaf(wv.x, x0, fmaf(wv.y, x1, fmaf(wv.z, x2, fmaf(wv.w, x3, a[g]))));
            }
        }
        #pragma unroll
        for (int g = 0; g < 4; g++) part[g][u][q][lane] = a[g];
        __syncthreads();

        if (tid < 64) {
            int uu = tid >> 5, b = tid & 31;
            int jj = blk * 2 + uu;
            float gv[4];
            #pragma unroll
            for (int g = 0; g < 4; g++)
                gv[g] = part[g][uu][0][b] + part[g][uu][1][b] + part[g][uu][2][b] +
                        part[g][uu][3][b] + g_bsum1[g * 256 + jj];
            float cv = g_c1[jj * 32 + b];
            float c2 = sigf(gv[1]) * cv + sigf(gv[0]) * tanhf(gv[2]);
            float h2 = sigf(gv[3]) * tanhf(c2);
            g_c1[jj * 32 + b] = c2;
            g_h1T[p ^ 1][jj * 32 + b] = h2;
        }
    }
}

// ---------------- attention + proj + copy gate + scatter (1 block per batch) ----------------
__global__ void __launch_bounds__(256) kAtt(
        const float* __restrict__ enc_mem, const float* __restrict__ enc_proj,
        const int* __restrict__ mask, const int* __restrict__ extend_art,
        const float* __restrict__ attn_w, const float* __restrict__ projW,
        const float* __restrict__ projb,
        const float* __restrict__ v_c, const float* __restrict__ v_s,
        const float* __restrict__ v_i, const float* __restrict__ copy_b,
        const float* __restrict__ emb, const int* __restrict__ abstract, int t) {
    __shared__ float ls[256], qs[256], as_[LL], red[256];
    __shared__ float s_gate;
    const int b = blockIdx.x, tid = threadIdx.x;
    const int pr = (t & 1) ^ 1;

    ls[tid] = g_h1T[pr][tid * 32 + b];
    if (tid == 0) g_sum[b] = 0.f;      // zero for kLogitsOut of this step
    __syncthreads();

    // query = lstm_out @ attn_w   (16 accumulators -> deep MLP over 234-cyc L2 loads)
    {
        float qa[16];
        #pragma unroll
        for (int j = 0; j < 16; j++) qa[j] = 0.f;
        for (int k = 0; k < 256; k += 16) {
            #pragma unroll
            for (int j = 0; j < 16; j++)
                qa[j] = fmaf(ls[k + j], attn_w[(k + j) * 256 + tid], qa[j]);
        }
        float s = 0.f;
        #pragma unroll
        for (int j = 0; j < 16; j++) s += qa[j];
        qs[tid] = s;
    }
    __syncthreads();

    // masked scores; small magnitudes -> max-free softmax is safe
    int anym = 0;
    for (int l = tid; l < LL; l += 256) {
        const float4* ep = (const float4*)(enc_proj + ((size_t)b * LL + l) * 256);
        float s0 = 0, s1 = 0;
        #pragma unroll 8
        for (int k4 = 0; k4 < 64; k4++) {
            float4 e = ep[k4];
            s0 = fmaf(qs[k4 * 4 + 0], e.x, fmaf(qs[k4 * 4 + 1], e.y, s0));
            s1 = fmaf(qs[k4 * 4 + 2], e.z, fmaf(qs[k4 * 4 + 3], e.w, s1));
        }
        int m = (mask[b * LL + l] != 0);
        anym |= m;
        as_[l] = m ? (s0 + s1) : -1e18f;
    }
    int any = __syncthreads_or(anym);

    float ps = 0.f;
    for (int l = tid; l < LL; l += 256) {
        float e = any ? __expf(as_[l]) : 1.0f;   // all-masked -> uniform
        as_[l] = e;
        ps += e;
    }
    red[tid] = ps; __syncthreads();
    for (int s = 128; s > 0; s >>= 1) { if (tid < s) red[tid] += red[tid + s]; __syncthreads(); }
    float inv = 1.0f / red[0];
    __syncthreads();
    for (int l = tid; l < LL; l += 256) as_[l] *= inv;
    __syncthreads();

    // ctx   (16 accumulators, 400 = 25*16)
    {
        float ca[16];
        #pragma unroll
        for (int j = 0; j < 16; j++) ca[j] = 0.f;
        const float* em = enc_mem + (size_t)b * LL * 256 + tid;
        for (int l = 0; l < LL; l += 16) {
            #pragma unroll
            for (int j = 0; j < 16; j++)
                ca[j] = fmaf(as_[l + j], em[(size_t)(l + j) * 256], ca[j]);
        }
        float s = 0.f;
        #pragma unroll
        for (int j = 0; j < 16; j++) s += ca[j];
        __syncthreads();              // everyone done reading qs (query)
        qs[tid] = s;                  // qs now holds ctx
    }
    __syncthreads();

    // dec_out = [ls | ctx] @ projW^T + projb
    {
        const float4* pw = (const float4*)(projW + (size_t)tid * 512);
        float d0 = projb[tid], d1 = 0.f;
        #pragma unroll 8
        for (int k4 = 0; k4 < 64; k4++) {
            float4 wv = pw[k4];
            d0 = fmaf(ls[k4 * 4 + 0], wv.x, fmaf(ls[k4 * 4 + 1], wv.y, d0));
            d1 = fmaf(ls[k4 * 4 + 2], wv.z, fmaf(ls[k4 * 4 + 3], wv.w, d1));
        }
        #pragma unroll 8
        for (int k4 = 64; k4 < 128; k4++) {
            float4 wv = pw[k4];
            int k = (k4 - 64) * 4;
            d0 = fmaf(qs[k + 0], wv.x, fmaf(qs[k + 1], wv.y, d0));
            d1 = fmaf(qs[k + 2], wv.z, fmaf(qs[k + 3], wv.w, d1));
        }
        g_pout[b * 256 + tid] = d0 + d1;
    }

    // copy gate
    {
        int tok = abstract[b * TT + t];
        float gp = qs[tid] * v_c[tid] + ls[tid] * v_s[tid] + emb[(size_t)tok * 256 + tid] * v_i[tid];
        red[tid] = gp; __syncthreads();
        for (int s = 128; s > 0; s >>= 1) { if (tid < s) red[tid] += red[tid + s]; __syncthreads(); }
        if (tid == 0) {
            float g = sigf(red[0] + copy_b[0]);
            s_gate = g;
            g_gate[b] = g;
        }
        __syncthreads();
    }

    // copy scatter (g_add zeroed by kGatesFused of this step)
    float gg = s_gate;
    for (int l = tid; l < LL; l += 256)
        atomicAdd(&g_add[b * EXT_V + extend_art[b * LL + l]], as_[l] * gg);
}

// ---------------- logits GEMM (smem-tiled) + exp + sums + grid-sync + output ----------------
// grid NBLK=148 (all wave-1 resident -> spin safe), block 256.
__global__ void __launch_bounds__(256) kLogitsOut(
        const float* __restrict__ emb, float* __restrict__ out, int t) {
    extern __shared__ char dyn[];
    float* semb = (float*)dyn;                          // 128*PITCH floats = 33792B
    u64* sdec   = (u64*)(dyn + 128 * PITCH * 4);        // 32*128 u64 = 32768B
    float* ssum = (float*)(dyn + 128 * PITCH * 4 + 32768);
    float* sscale = ssum + 32;
    const int tid = threadIdx.x;

    for (int i = tid; i < 4096; i += 256)               // dec packed k-pairs, [b][kp]
        sdec[i] = *(const u64*)(g_pout + (i >> 7) * 256 + (i & 127) * 2);
    if (tid < 32) ssum[tid] = 0.f;

    const int tb = tid >> 5;            // warp -> batches 4tb..4tb+3
    const int tv = tid & 31;            // lane -> v rows tv+32j
    const int v0 = (int)((long long)blockIdx.x * VV / NBLK);
    const int v1 = (int)((long long)(blockIdx.x + 1) * VV / NBLK);

    float lsum[4] = {0.f, 0.f, 0.f, 0.f};

    for (int vt = v0; vt < v1; vt += 128) {
        u64 acc[4][4];                  // [j: v][i: b]
        #pragma unroll
        for (int j = 0; j < 4; j++)
            #pragma unroll
            for (int i = 0; i < 4; i++) acc[j][i] = 0ull;

        for (int kc = 0; kc < 4; kc++) {
            __syncthreads();            // prior reads of semb done
            #pragma unroll
            for (int it = 0; it < 8; it++) {   // fill 128 rows x 64 floats, coalesced
                int i = it * 256 + tid;
                int r = i >> 4, qq = i & 15;
                int vr = vt + r; if (vr > VV - 1) vr = VV - 1;
                float4 v = *(const float4*)(emb + (size_t)vr * 256 + kc * 64 + qq * 4);
                float* d = semb + r * PITCH + qq * 4;
                d[0] = v.x; d[1] = v.y; d[2] = v.z; d[3] = v.w;
            }
            __syncthreads();
            const u64* dp = sdec + (tb * 4) * 128 + kc * 32;
            #pragma unroll 2
            for (int kp = 0; kp < 32; kp++) {
                u64 d0 = dp[kp], d1 = dp[128 + kp], d2 = dp[256 + kp], d3 = dp[384 + kp];
                #pragma unroll
                for (int j = 0; j < 4; j++) {
                    u64 e = *(const u64*)(semb + (tv + 32 * j) * PITCH + kp * 2);
                    acc[j][0] = ffma2(e, d0, acc[j][0]);
                    acc[j][1] = ffma2(e, d1, acc[j][1]);
                    acc[j][2] = ffma2(e, d2, acc[j][2]);
                    acc[j][3] = ffma2(e, d3, acc[j][3]);
                }
            }
        }
        #pragma unroll
        for (int j = 0; j < 4; j++) {
            int v = vt + tv + 32 * j;
            if (v < v1) {
                #pragma unroll
                for (int i = 0; i < 4; i++) {
                    float pz = __expf(sum2(acc[j][i]));
                    g_scr[(size_t)(4 * tb + i) * VV + v] = pz;
                    lsum[i] += pz;
                }
            }
        }
    }
    // per-warp reduce (all lanes of a warp share the same 4 batches)
    #pragma unroll
    for (int i = 0; i < 4; i++) {
        float v = lsum[i];
        #pragma unroll
        for (int o = 16; o > 0; o >>= 1) v += __shfl_xor_sync(0xffffffffu, v, o);
        if (tv == 0) atomicAdd(&ssum[4 * tb + i], v);
    }
    __syncthreads();
    if (tid < 32) atomicAdd(&g_sum[tid], ssum[tid]);

    // ---- grid-wide sync: all 148 blocks posted their partial sums ----
    __threadfence();
    if (tid == 0) {
        atomicAdd(&g_cnt, 1u);
        const unsigned target = (unsigned)NBLK * (unsigned)(t + 1);
        while (*((volatile unsigned*)&g_cnt) < target) { __nanosleep(64); }
    }
    __syncthreads();
    __threadfence();

    if (tid < 32) sscale[tid] = (1.0f - g_gate[tid]) / g_sum[tid];
    __syncthreads();

    // ---- final output for this block's v-range, all batches ----
    for (int b = 0; b < BB; b++) {
        float scale = sscale[b];
        const float* sc = g_scr + (size_t)b * VV;
        const float* ad = g_add + (size_t)b * EXT_V;
        float* ob = out + ((size_t)b * TT + t) * EXT_V;
        for (int v = v0 + tid; v < v1; v += 256)
            ob[v] = __logf(sc[v] * scale + ad[v] + 1e-12f);
    }
    // pad region v in [VV, EXT_V): gen term is exactly 0 (matches -1e8 pad underflow)
    if (blockIdx.x < EXT_V - VV && tid < BB) {
        int vp = VV + blockIdx.x;
        out[((size_t)tid * TT + t) * EXT_V + vp] = __logf(g_add[(size_t)tid * EXT_V + vp] + 1e-12f);
    }
}

// ---------------- launch ----------------
extern "C" void kernel_launch(void* const* d_in, const int* in_sizes, int n_in,
                              void* d_out, int out_size) {
    const int S = (n_in >= 25) ? 1 : 0;   // extend_vsize scalar present or not
    const int* abstract        = (const int*)d_in[0];
    const float* enc_mem       = (const float*)d_in[1];
    const float* enc_proj      = (const float*)d_in[2];
    const int* mask            = (const int*)d_in[3];
    const int* extend_art      = (const int*)d_in[4];
    const float* h0            = (const float*)d_in[5 + S];
    const float* c0            = (const float*)d_in[6 + S];
    const float* pout          = (const float*)d_in[7 + S];
    const float* emb           = (const float*)d_in[8 + S];
    const float* Wih0          = (const float*)d_in[9 + S];
    const float* Whh0          = (const float*)d_in[10 + S];
    const float* bih0          = (const float*)d_in[11 + S];
    const float* bhh0          = (const float*)d_in[12 + S];
    const float* Wih1          = (const float*)d_in[13 + S];
    const float* Whh1          = (const float*)d_in[14 + S];
    const float* bih1          = (const float*)d_in[15 + S];
    const float* bhh1          = (const float*)d_in[16 + S];
    const float* attn_w        = (const float*)d_in[17 + S];
    const float* projW         = (const float*)d_in[18 + S];
    const float* projb         = (const float*)d_in[19 + S];
    const float* v_c           = (const float*)d_in[20 + S];
    const float* v_s           = (const float*)d_in[21 + S];
    const float* v_i           = (const float*)d_in[22 + S];
    const float* copy_b        = (const float*)d_in[23 + S];
    float* out = (float*)d_out;

    const int smemG = (25344 + 1536 * 4) * 4;             // xs + 8x768 W floats = 125952B
    const int smemL = 128 * PITCH * 4 + 32768 + 64 * 4;   // semb + sdec + ssum/sscale
    cudaFuncSetAttribute(kGatesFused, cudaFuncAttributeMaxDynamicSharedMemorySize, smemG);
    cudaFuncSetAttribute(kLogitsOut, cudaFuncAttributeMaxDynamicSharedMemorySize, smemL);

    kPrep<<<5128, 256>>>(Wih0, Whh0, bih0, bhh0, Wih1, Whh1, bih1, bhh1);
    kInit<<<32, 256>>>(h0, c0, pout);
    for (int t = 0; t < TT; t++) {
        kGatesFused<<<GBLK, 256, smemG>>>(emb, abstract, extend_art, t);
        kAtt<<<32, 256>>>(enc_mem, enc_proj, mask, extend_art, attn_w, projW, projb,
                          v_c, v_s, v_i, copy_b, emb, abstract, t);
        kLogitsOut<<<NBLK, 256, smemL>>>(emb, out, t);
    }
}

// round 17
// speedup vs baseline: 2.6277x; 1.2350x over previous
#include <cuda_runtime.h>
#include <cuda_bf16.h>
#include <cstdint>

#define BB 32
#define TT 48
#define LL 400
#define VV 32000
#define EXT_V 32050
#define NBLK 148
#define GBLK 128
#define ABLK 128
#define PITCH 66   // words per 64-float semb row; even (8B align), bank-stride 2

typedef unsigned long long u64;

// ---------------- persistent device state ----------------
__device__ float g_Wcat0[1024 * 768];   // [Wih0 | Whh0]
__device__ float g_Wcat1[1024 * 512];   // [Wih1 | Whh1]
__device__ float g_attnT[256 * 256];    // attn_w transposed: [d][k]
__device__ float g_bsum0[1024];
__device__ float g_bsum1[1024];
__device__ float g_h0T[2][8192];        // [parity][j*32+b]
__device__ float g_h1T[2][8192];
__device__ float g_c0[8192];            // [j*32+b], in-place
__device__ float g_c1[8192];
__device__ float g_pout[8192];          // dec_out / prev_out, [b*256+e]
__device__ float g_query[8192];         // [b*256+d]
__device__ float g_attnE[BB * LL];      // exp(score) (unnormalized)
__device__ float g_asum[BB];
__device__ float g_ctx[8192];           // [b*256+d]
__device__ int   g_anym[BB];            // any-unmasked flag (static per input)
__device__ float g_gate[BB];
__device__ float g_sum[BB];
__device__ unsigned g_cnt;              // kLogitsOut counter (reset each replay)
__device__ unsigned g_cnt2;             // kGatesFused counter
__device__ unsigned g_cnt3;             // kAttP counter (3 phases/step)
__device__ float g_scr[BB * VV];        // exp(logits), [b][v]
__device__ float g_add[BB * EXT_V];     // copy-scatter buffer

__device__ __forceinline__ float sigf(float x) { return 1.0f / (1.0f + __expf(-x)); }

__device__ __forceinline__ u64 ffma2(u64 a, u64 b, u64 c) {
    u64 r;
    asm("fma.rn.f32x2 %0, %1, %2, %3;" : "=l"(r) : "l"(a), "l"(b), "l"(c));
    return r;
}
__device__ __forceinline__ float sum2(u64 v) {
    float a, b;
    asm("mov.b64 {%0, %1}, %2;" : "=f"(a), "=f"(b) : "l"(v));
    return a + b;
}
// grid-wide spin barrier (all blocks wave-1 resident; counter reset per replay)
__device__ __forceinline__ void gspin(unsigned* cnt, unsigned target) {
    __threadfence();
    if (threadIdx.x == 0) {
        atomicAdd(cnt, 1u);
        while (*((volatile unsigned*)cnt) < target) { __nanosleep(32); }
    }
    __syncthreads();
    __threadfence();
}

// ---------------- prep: concat weights, transpose attn_w, sum biases ----------------
__global__ void __launch_bounds__(256) kPrep(
        const float* __restrict__ Wih0, const float* __restrict__ Whh0,
        const float* __restrict__ bih0, const float* __restrict__ bhh0,
        const float* __restrict__ Wih1, const float* __restrict__ Whh1,
        const float* __restrict__ bih1, const float* __restrict__ bhh1,
        const float* __restrict__ attn_w) {
    int i = blockIdx.x * 256 + threadIdx.x;
    if (i < 1024 * 768) {
        int r = i / 768, k = i - r * 768;
        g_Wcat0[i] = (k < 512) ? Wih0[r * 512 + k] : Whh0[r * 256 + (k - 512)];
        return;
    }
    int j = i - 1024 * 768;
    if (j < 1024 * 512) {
        int r = j / 512, k = j - r * 512;
        g_Wcat1[j] = (k < 256) ? Wih1[r * 256 + k] : Whh1[r * 256 + (k - 256)];
        return;
    }
    int m = j - 1024 * 512;
    if (m < 1024) { g_bsum0[m] = bih0[m] + bhh0[m]; return; }
    if (m < 2048) { g_bsum1[m - 1024] = bih1[m - 1024] + bhh1[m - 1024]; return; }
    int m2 = m - 2048;
    if (m2 < 65536) g_attnT[m2] = attn_w[(m2 & 255) * 256 + (m2 >> 8)];
}

// ---------------- init state (every replay) ----------------
__global__ void __launch_bounds__(256) kInit(
        const float* __restrict__ h0, const float* __restrict__ c0,
        const float* __restrict__ pout, const int* __restrict__ mask) {
    int i = blockIdx.x * 256 + threadIdx.x;   // i = b*256 + j
    if (i == 0) { g_cnt = 0u; g_cnt2 = 0u; g_cnt3 = 0u; }
    if (blockIdx.x == 0 && threadIdx.x < 32) {      // any-unmasked per batch (static)
        int b = threadIdx.x, m = 0;
        for (int l = 0; l < LL; l++) m |= (mask[b * LL + l] != 0);
        g_anym[b] = m;
    }
    if (i >= 8192) return;
    int b = i >> 8, j = i & 255;
    g_h0T[0][j * 32 + b] = h0[i];
    g_h1T[0][j * 32 + b] = h0[8192 + i];
    g_c0[j * 32 + b] = c0[i];
    g_c1[j * 32 + b] = c0[8192 + i];
    g_pout[i] = pout[i];
}

// ---------------- fused LSTM layers 0+1 (grid-spin between) ----------------
__global__ void __launch_bounds__(256) kGatesFused(
        const float* __restrict__ emb, const int* __restrict__ abstract,
        const int* __restrict__ extend_art, int t) {
    extern __shared__ float xs[];                 // [768][33] = 25344 floats
    float4* sw4 = (float4*)(xs + 25344);
    __shared__ float part[4][2][4][32];
    __shared__ int toks[32];
    const int tid = threadIdx.x;
    const int p = t & 1;
    const int blk = blockIdx.x;
    const int w = tid >> 5, lane = tid & 31;
    const int u = w & 1, q = w >> 1;

    // ================= Phase A: layer 0 =================
    {
        int gid = blk * 256 + tid;                // zero copy-scatter targets (static positions)
        if (gid < BB * LL) {
            int b = gid / LL, l = gid - b * LL;
            g_add[b * EXT_V + extend_art[b * LL + l]] = 0.f;
        }
        if (blk == 0 && tid < 32) g_sum[tid] = 0.f;   // for kLogitsOut of this step
        if (tid < 32) toks[tid] = abstract[tid * TT + t];
        __syncthreads();
        #pragma unroll
        for (int it = 0; it < 8; it++) {          // emb rows
            int i = it * 256 + tid;
            int b = i >> 6, qq = i & 63;
            float4 v = *(const float4*)(emb + (size_t)toks[b] * 256 + qq * 4);
            float* d = xs + (4 * qq) * 33 + b;
            d[0] = v.x; d[33] = v.y; d[66] = v.z; d[99] = v.w;
        }
        #pragma unroll
        for (int it = 0; it < 8; it++) {          // prev dec_out
            int i = it * 256 + tid;
            int b = i >> 6, qq = i & 63;
            float4 v = *(const float4*)(g_pout + b * 256 + qq * 4);
            float* d = xs + (256 + 4 * qq) * 33 + b;
            d[0] = v.x; d[33] = v.y; d[66] = v.z; d[99] = v.w;
        }
        #pragma unroll
        for (int it = 0; it < 8; it++) {          // h0 prev
            int i = it * 256 + tid;
            int k = i >> 3, b4 = (i & 7) * 4;
            float4 v = *(const float4*)(g_h0T[p] + k * 32 + b4);
            float* d = xs + (512 + k) * 33 + b4;
            d[0] = v.x; d[1] = v.y; d[2] = v.z; d[3] = v.w;
        }
        #pragma unroll
        for (int it = 0; it < 6; it++) {          // W rows
            int i = it * 256 + tid;
            int r = i / 192, c = i - r * 192;
            sw4[i] = ((const float4*)(g_Wcat0 + (size_t)((r >> 1) * 256 + blk * 2 + (r & 1)) * 768))[c];
        }
        __syncthreads();

        const float4* wr[4];
        #pragma unroll
        for (int g = 0; g < 4; g++) wr[g] = sw4 + (g * 2 + u) * 192 + q * 48;
        const float* xq = xs + (q * 192) * 33 + lane;

        float a[4] = {0.f, 0.f, 0.f, 0.f};
        #pragma unroll 4
        for (int k4 = 0; k4 < 48; k4++) {
            float x0 = xq[(4 * k4 + 0) * 33], x1 = xq[(4 * k4 + 1) * 33];
            float x2 = xq[(4 * k4 + 2) * 33], x3 = xq[(4 * k4 + 3) * 33];
            #pragma unroll
            for (int g = 0; g < 4; g++) {
                float4 wv = wr[g][k4];
                a[g] = fmaf(wv.x, x0, fmaf(wv.y, x1, fmaf(wv.z, x2, fmaf(wv.w, x3, a[g]))));
            }
        }
        #pragma unroll
        for (int g = 0; g < 4; g++) part[g][u][q][lane] = a[g];
        __syncthreads();

        if (tid < 64) {
            int uu = tid >> 5, b = tid & 31;
            int jj = blk * 2 + uu;
            float gv[4];
            #pragma unroll
            for (int g = 0; g < 4; g++)
                gv[g] = part[g][uu][0][b] + part[g][uu][1][b] + part[g][uu][2][b] +
                        part[g][uu][3][b] + g_bsum0[g * 256 + jj];
            float cv = g_c0[jj * 32 + b];
            float c2 = sigf(gv[1]) * cv + sigf(gv[0]) * tanhf(gv[2]);
            float h2 = sigf(gv[3]) * tanhf(c2);
            g_c0[jj * 32 + b] = c2;
            g_h0T[p ^ 1][jj * 32 + b] = h2;
        }
        __syncthreads();
    }

    gspin(&g_cnt2, (unsigned)GBLK * (unsigned)(t + 1));

    // ================= Phase B: layer 1 =================
    {
        #pragma unroll
        for (int it = 0; it < 8; it++) {          // h0 new
            int i = it * 256 + tid;
            int k = i >> 3, b4 = (i & 7) * 4;
            float4 v = *(const float4*)(g_h0T[p ^ 1] + k * 32 + b4);
            float* d = xs + k * 33 + b4;
            d[0] = v.x; d[1] = v.y; d[2] = v.z; d[3] = v.w;
        }
        #pragma unroll
        for (int it = 0; it < 8; it++) {          // h1 prev
            int i = it * 256 + tid;
            int k = i >> 3, b4 = (i & 7) * 4;
            float4 v = *(const float4*)(g_h1T[p] + k * 32 + b4);
            float* d = xs + (256 + k) * 33 + b4;
            d[0] = v.x; d[1] = v.y; d[2] = v.z; d[3] = v.w;
        }
        #pragma unroll
        for (int it = 0; it < 4; it++) {          // W rows
            int i = it * 256 + tid;
            int r = i >> 7, c = i & 127;
            sw4[i] = ((const float4*)(g_Wcat1 + (size_t)((r >> 1) * 256 + blk * 2 + (r & 1)) * 512))[c];
        }
        __syncthreads();

        const float4* wr[4];
        #pragma unroll
        for (int g = 0; g < 4; g++) wr[g] = sw4 + (g * 2 + u) * 128 + q * 32;
        const float* xq = xs + (q * 128) * 33 + lane;

        float a[4] = {0.f, 0.f, 0.f, 0.f};
        #pragma unroll 4
        for (int k4 = 0; k4 < 32; k4++) {
            float x0 = xq[(4 * k4 + 0) * 33], x1 = xq[(4 * k4 + 1) * 33];
            float x2 = xq[(4 * k4 + 2) * 33], x3 = xq[(4 * k4 + 3) * 33];
            #pragma unroll
            for (int g = 0; g < 4; g++) {
                float4 wv = wr[g][k4];
                a[g] = fmaf(wv.x, x0, fmaf(wv.y, x1, fmaf(wv.z, x2, fmaf(wv.w, x3, a[g]))));
            }
        }
        #pragma unroll
        for (int g = 0; g < 4; g++) part[g][u][q][lane] = a[g];
        __syncthreads();

        if (tid < 64) {
            int uu = tid >> 5, b = tid & 31;
            int jj = blk * 2 + uu;
            float gv[4];
            #pragma unroll
            for (int g = 0; g < 4; g++)
                gv[g] = part[g][uu][0][b] + part[g][uu][1][b] + part[g][uu][2][b] +
                        part[g][uu][3][b] + g_bsum1[g * 256 + jj];
            float cv = g_c1[jj * 32 + b];
            float c2 = sigf(gv[1]) * cv + sigf(gv[0]) * tanhf(gv[2]);
            float h2 = sigf(gv[3]) * tanhf(c2);
            g_c1[jj * 32 + b] = c2;
            g_h1T[p ^ 1][jj * 32 + b] = h2;
        }
    }
}

// ---------------- attention, persistent 128 blocks, 3 grid-spins ----------------
// P1 query (+zero ctx/asum) | P2 scores+exp+partial sums | P3 ctx partials | P4 dec_out+gate
__global__ void __launch_bounds__(256) kAttP(
        const float* __restrict__ enc_mem, const float* __restrict__ enc_proj,
        const int* __restrict__ mask,
        const float* __restrict__ projW, const float* __restrict__ projb,
        const float* __restrict__ v_c, const float* __restrict__ v_s,
        const float* __restrict__ v_i, const float* __restrict__ copy_b,
        const float* __restrict__ emb, const int* __restrict__ abstract, int t) {
    __shared__ float s1[256], s2[256], sred[256];
    const int tid = threadIdx.x, blk = blockIdx.x;
    const int pr = (t & 1) ^ 1;

    // ---- P1: query[b][d-range]; zero g_ctx range + g_asum ----
    {
        int b = blk & 31, qd = blk >> 5;
        s1[tid] = g_h1T[pr][tid * 32 + b];        // ls[k]
        if (tid < 64) g_ctx[b * 256 + qd * 64 + tid] = 0.f;
        if (qd == 0 && tid == 0) g_asum[b] = 0.f;
        __syncthreads();
        int d = qd * 64 + (tid >> 2);
        int k0 = (tid & 3) * 64;
        const float4* wt = (const float4*)(g_attnT + (size_t)d * 256 + k0);
        float acc[8] = {0, 0, 0, 0, 0, 0, 0, 0};
        #pragma unroll
        for (int i = 0; i < 16; i++) {
            float4 wv = wt[i];
            int k = k0 + i * 4;
            acc[i & 7] = fmaf(wv.x, s1[k], fmaf(wv.y, s1[k + 1],
                         fmaf(wv.z, s1[k + 2], fmaf(wv.w, s1[k + 3], acc[i & 7]))));
        }
        float r = ((acc[0] + acc[1]) + (acc[2] + acc[3])) + ((acc[4] + acc[5]) + (acc[6] + acc[7]));
        sred[tid] = r;
        __syncthreads();
        if ((tid & 3) == 0)
            g_query[b * 256 + d] = sred[tid] + sred[tid + 1] + sred[tid + 2] + sred[tid + 3];
    }
    gspin(&g_cnt3, (unsigned)ABLK * (unsigned)(3 * t + 1));

    // ---- P2: scores for (b, 100 l's) -> exp -> g_attnE, partial sums -> g_asum ----
    {
        int b = blk >> 2, l0 = (blk & 3) * 100;
        s1[tid] = g_query[b * 256 + tid];
        __syncthreads();
        const int w = tid >> 5, lane = tid & 31;
        float qreg[8];
        #pragma unroll
        for (int j = 0; j < 8; j++) qreg[j] = s1[lane * 8 + j];
        const int any = g_anym[b];
        float psum = 0.f;
        #pragma unroll
        for (int i = 0; i < 13; i++) {
            int lo = w + 8 * i;
            if (lo < 100) {
                int l = l0 + lo;
                const float4* ep = (const float4*)(enc_proj + ((size_t)b * LL + l) * 256 + lane * 8);
                float4 e0 = ep[0], e1 = ep[1];
                float s = qreg[0] * e0.x + qreg[1] * e0.y + qreg[2] * e0.z + qreg[3] * e0.w +
                          qreg[4] * e1.x + qreg[5] * e1.y + qreg[6] * e1.z + qreg[7] * e1.w;
                #pragma unroll
                for (int o = 16; o > 0; o >>= 1) s += __shfl_xor_sync(0xffffffffu, s, o);
                if (lane == 0) {
                    int m = (mask[b * LL + l] != 0);
                    float e = any ? (m ? __expf(s) : 0.f) : 1.0f;
                    g_attnE[b * LL + l] = e;
                    psum += e;
                }
            }
        }
        if (lane == 0) sred[w] = psum;
        __syncthreads();
        if (tid == 0) {
            float s = ((sred[0] + sred[1]) + (sred[2] + sred[3])) +
                      ((sred[4] + sred[5]) + (sred[6] + sred[7]));
            atomicAdd(&g_asum[b], s);
        }
    }
    gspin(&g_cnt3, (unsigned)ABLK * (unsigned)(3 * t + 2));

    // ---- P3: ctx partials for (b, 100 l's) -> atomicAdd g_ctx ----
    {
        int b = blk >> 2, l0 = (blk & 3) * 100;
        if (tid < 100) s2[tid] = g_attnE[b * LL + l0 + tid];
        __syncthreads();
        float inv = 1.0f / g_asum[b];
        const float* em = enc_mem + ((size_t)b * LL + l0) * 256 + tid;
        float ca[20];
        #pragma unroll
        for (int j = 0; j < 20; j++) ca[j] = 0.f;
        #pragma unroll
        for (int i = 0; i < 5; i++) {
            #pragma unroll
            for (int j = 0; j < 20; j++) {
                int l = i * 20 + j;
                ca[j] = fmaf(s2[l], em[(size_t)l * 256], ca[j]);
            }
        }
        float s = 0.f;
        #pragma unroll
        for (int j = 0; j < 20; j++) s += ca[j];
        atomicAdd(&g_ctx[b * 256 + tid], s * inv);
    }
    gspin(&g_cnt3, (unsigned)ABLK * (unsigned)(3 * t + 3));

    // ---- P4: dec_out + copy gate ----
    {
        int b = blk & 31, qe = blk >> 5;
        s1[tid] = g_h1T[pr][tid * 32 + b];        // ls
        s2[tid] = g_ctx[b * 256 + tid];           // ctx
        __syncthreads();
        int e = qe * 64 + (tid >> 2), ks = tid & 3;
        const float4* pw = (const float4*)(projW + (size_t)e * 512 + ks * 128);
        const float* xb = (ks < 2) ? (s1 + ks * 128) : (s2 + (ks - 2) * 128);
        float acc[8] = {0, 0, 0, 0, 0, 0, 0, 0};
        #pragma unroll
        for (int i = 0; i < 32; i++) {
            float4 wv = pw[i];
            acc[i & 7] = fmaf(wv.x, xb[4 * i], fmaf(wv.y, xb[4 * i + 1],
                         fmaf(wv.z, xb[4 * i + 2], fmaf(wv.w, xb[4 * i + 3], acc[i & 7]))));
        }
        float r = ((acc[0] + acc[1]) + (acc[2] + acc[3])) + ((acc[4] + acc[5]) + (acc[6] + acc[7]));
        sred[tid] = r;
        __syncthreads();
        if ((tid & 3) == 0)
            g_pout[b * 256 + e] = sred[tid] + sred[tid + 1] + sred[tid + 2] + sred[tid + 3] + projb[e];

        if (qe == 0) {    // copy gate (block-uniform branch)
            __syncthreads();
            int tok = abstract[b * TT + t];
            float gp = s2[tid] * v_c[tid] + s1[tid] * v_s[tid] + emb[(size_t)tok * 256 + tid] * v_i[tid];
            sred[tid] = gp;
            __syncthreads();
            for (int s = 128; s > 0; s >>= 1) { if (tid < s) sred[tid] += sred[tid + s]; __syncthreads(); }
            if (tid == 0) g_gate[b] = sigf(sred[0] + copy_b[0]);
        }
    }
}

// ---------------- logits GEMM (smem-tiled) + scatter + exp + sums + grid-sync + output ----------------
__global__ void __launch_bounds__(256) kLogitsOut(
        const float* __restrict__ emb, const int* __restrict__ extend_art,
        float* __restrict__ out, int t) {
    extern __shared__ char dyn[];
    float* semb = (float*)dyn;                          // 128*PITCH floats
    u64* sdec   = (u64*)(dyn + 128 * PITCH * 4);        // 32*128 u64
    float* ssum = (float*)(dyn + 128 * PITCH * 4 + 32768);
    float* sscale = ssum + 32;
    const int tid = threadIdx.x;

    // copy scatter (needs g_gate/g_asum from kAttP; g_add zeroed by kGatesFused this step)
    {
        int i0 = (int)((long long)blockIdx.x * (BB * LL) / NBLK);
        int i1 = (int)((long long)(blockIdx.x + 1) * (BB * LL) / NBLK);
        for (int i = i0 + tid; i < i1; i += 256) {
            int b = i / LL;
            float val = g_attnE[i] * (g_gate[b] / g_asum[b]);
            atomicAdd(&g_add[(size_t)b * EXT_V + extend_art[i]], val);
        }
    }

    for (int i = tid; i < 4096; i += 256)               // dec packed k-pairs, [b][kp]
        sdec[i] = *(const u64*)(g_pout + (i >> 7) * 256 + (i & 127) * 2);
    if (tid < 32) ssum[tid] = 0.f;

    const int tb = tid >> 5;            // warp -> batches 4tb..4tb+3
    const int tv = tid & 31;            // lane -> v rows tv+32j
    const int v0 = (int)((long long)blockIdx.x * VV / NBLK);
    const int v1 = (int)((long long)(blockIdx.x + 1) * VV / NBLK);

    float lsum[4] = {0.f, 0.f, 0.f, 0.f};

    for (int vt = v0; vt < v1; vt += 128) {
        u64 acc[4][4];
        #pragma unroll
        for (int j = 0; j < 4; j++)
            #pragma unroll
            for (int i = 0; i < 4; i++) acc[j][i] = 0ull;

        for (int kc = 0; kc < 4; kc++) {
            __syncthreads();
            #pragma unroll
            for (int it = 0; it < 8; it++) {
                int i = it * 256 + tid;
                int r = i >> 4, qq = i & 15;
                int vr = vt + r; if (vr > VV - 1) vr = VV - 1;
                float4 v = *(const float4*)(emb + (size_t)vr * 256 + kc * 64 + qq * 4);
                float* d = semb + r * PITCH + qq * 4;
                d[0] = v.x; d[1] = v.y; d[2] = v.z; d[3] = v.w;
            }
            __syncthreads();
            const u64* dp = sdec + (tb * 4) * 128 + kc * 32;
            #pragma unroll 2
            for (int kp = 0; kp < 32; kp++) {
                u64 d0 = dp[kp], d1 = dp[128 + kp], d2 = dp[256 + kp], d3 = dp[384 + kp];
                #pragma unroll
                for (int j = 0; j < 4; j++) {
                    u64 e = *(const u64*)(semb + (tv + 32 * j) * PITCH + kp * 2);
                    acc[j][0] = ffma2(e, d0, acc[j][0]);
                    acc[j][1] = ffma2(e, d1, acc[j][1]);
                    acc[j][2] = ffma2(e, d2, acc[j][2]);
                    acc[j][3] = ffma2(e, d3, acc[j][3]);
                }
            }
        }
        #pragma unroll
        for (int j = 0; j < 4; j++) {
            int v = vt + tv + 32 * j;
            if (v < v1) {
                #pragma unroll
                for (int i = 0; i < 4; i++) {
                    float pz = __expf(sum2(acc[j][i]));
                    g_scr[(size_t)(4 * tb + i) * VV + v] = pz;
                    lsum[i] += pz;
                }
            }
        }
    }
    #pragma unroll
    for (int i = 0; i < 4; i++) {
        float v = lsum[i];
        #pragma unroll
        for (int o = 16; o > 0; o >>= 1) v += __shfl_xor_sync(0xffffffffu, v, o);
        if (tv == 0) atomicAdd(&ssum[4 * tb + i], v);
    }
    __syncthreads();
    if (tid < 32) atomicAdd(&g_sum[tid], ssum[tid]);

    gspin(&g_cnt, (unsigned)NBLK * (unsigned)(t + 1));

    if (tid < 32) sscale[tid] = (1.0f - g_gate[tid]) / g_sum[tid];
    __syncthreads();

    for (int b = 0; b < BB; b++) {
        float scale = sscale[b];
        const float* sc = g_scr + (size_t)b * VV;
        const float* ad = g_add + (size_t)b * EXT_V;
        float* ob = out + ((size_t)b * TT + t) * EXT_V;
        for (int v = v0 + tid; v < v1; v += 256)
            ob[v] = __logf(sc[v] * scale + ad[v] + 1e-12f);
    }
    if (blockIdx.x < EXT_V - VV && tid < BB) {
        int vp = VV + blockIdx.x;
        out[((size_t)tid * TT + t) * EXT_V + vp] = __logf(g_add[(size_t)tid * EXT_V + vp] + 1e-12f);
    }
}

// ---------------- launch ----------------
extern "C" void kernel_launch(void* const* d_in, const int* in_sizes, int n_in,
                              void* d_out, int out_size) {
    const int S = (n_in >= 25) ? 1 : 0;   // extend_vsize scalar present or not
    const int* abstract        = (const int*)d_in[0];
    const float* enc_mem       = (const float*)d_in[1];
    const float* enc_proj      = (const float*)d_in[2];
    const int* mask            = (const int*)d_in[3];
    const int* extend_art      = (const int*)d_in[4];
    const float* h0            = (const float*)d_in[5 + S];
    const float* c0            = (const float*)d_in[6 + S];
    const float* pout          = (const float*)d_in[7 + S];
    const float* emb           = (const float*)d_in[8 + S];
    const float* Wih0          = (const float*)d_in[9 + S];
    const float* Whh0          = (const float*)d_in[10 + S];
    const float* bih0          = (const float*)d_in[11 + S];
    const float* bhh0          = (const float*)d_in[12 + S];
    const float* Wih1          = (const float*)d_in[13 + S];
    const float* Whh1          = (const float*)d_in[14 + S];
    const float* bih1          = (const float*)d_in[15 + S];
    const float* bhh1          = (const float*)d_in[16 + S];
    const float* attn_w        = (const float*)d_in[17 + S];
    const float* projW         = (const float*)d_in[18 + S];
    const float* projb         = (const float*)d_in[19 + S];
    const float* v_c           = (const float*)d_in[20 + S];
    const float* v_s           = (const float*)d_in[21 + S];
    const float* v_i           = (const float*)d_in[22 + S];
    const float* copy_b        = (const float*)d_in[23 + S];
    float* out = (float*)d_out;

    const int smemG = (25344 + 1536 * 4) * 4;             // 125952B
    const int smemL = 128 * PITCH * 4 + 32768 + 64 * 4;
    cudaFuncSetAttribute(kGatesFused, cudaFuncAttributeMaxDynamicSharedMemorySize, smemG);
    cudaFuncSetAttribute(kLogitsOut, cudaFuncAttributeMaxDynamicSharedMemorySize, smemL);

    kPrep<<<5384, 256>>>(Wih0, Whh0, bih0, bhh0, Wih1, Whh1, bih1, bhh1, attn_w);
    kInit<<<32, 256>>>(h0, c0, pout, mask);
    for (int t = 0; t < TT; t++) {
        kGatesFused<<<GBLK, 256, smemG>>>(emb, abstract, extend_art, t);
        kAttP<<<ABLK, 256>>>(enc_mem, enc_proj, mask, projW, projb,
                             v_c, v_s, v_i, copy_b, emb, abstract, t);
        kLogitsOut<<<NBLK, 256, smemL>>>(emb, extend_art, out, t);
    }
}